// round 4
// baseline (speedup 1.0000x reference)
#include <cuda_runtime.h>
#include <cstdint>

// Problem constants
#define BB 64
#define HH 128
#define WW 128
#define CC 16
#define UU 256
#define HWN (HH * WW)          // 16384

typedef unsigned long long ull;

// ---------------- scratch (device globals; no allocation allowed) ----------------
__device__ float g_S[HWN * BB];                 // S_t[hw][b], 4 MB
__device__ float g_GX1t[WW * UU];               // [w][u]
__device__ float g_GX2t[WW * UU];
__device__ float g_GY1t[HH * UU];               // [h][u], c1 folded in
__device__ float g_GY2t[HH * UU];               // [h][u], -c2 folded in
__device__ float g_P[HH * BB * UU];             // partials [h][b][u], 8 MB
__device__ float g_P2[8 * BB * UU];             // stage-2 partials, 512 KB

// ---------------- packed-fp32 helpers (guarded; fallback = scalar fmaf) ----------
__device__ __forceinline__ ull dup2(float s) {
    ull d; unsigned r = __float_as_uint(s);
    asm("mov.b64 %0, {%1, %1};" : "=l"(d) : "r"(r));
    return d;
}
__device__ __forceinline__ float f2lo(ull v) { return __uint_as_float((unsigned)v); }
__device__ __forceinline__ float f2hi(ull v) { return __uint_as_float((unsigned)(v >> 32)); }
__device__ __forceinline__ ull pack2(float lo, float hi) {
    ull d;
    asm("mov.b64 %0, {%1, %2};" : "=l"(d) : "r"(__float_as_uint(lo)), "r"(__float_as_uint(hi)));
    return d;
}
__device__ __forceinline__ void fma2(ull& d, ull a, ull b) {
#if defined(__CUDA_ARCH__) && (__CUDA_ARCH__ >= 1000)
    asm("fma.rn.f32x2 %0, %1, %2, %0;" : "+l"(d) : "l"(a), "l"(b));
#else
    float lo = fmaf(f2lo(a), f2lo(b), f2lo(d));
    float hi = fmaf(f2hi(a), f2hi(b), f2hi(d));
    d = pack2(lo, hi);
#endif
}

// ============================================================================
// K1: channel reduction + transpose.  S_t[(h*W+w)][b] = sum_c x[b][h][w][c]
// grid 256 blocks x 256 thr; block handles 64 consecutive hw for all 64 b.
// One thread fully sums one (b,hw): 4 consecutive float4 loads, no shuffles.
// 16 items/thread, unrolled -> high MLP. Transposed write via smem.
// ============================================================================
__global__ __launch_bounds__(256) void k1_reduce_c(const float* __restrict__ x) {
    const int hw0 = blockIdx.x * 64;
    __shared__ float s_s[64][65];
    const float4* x4 = reinterpret_cast<const float4*>(x);
    const int tid = threadIdx.x;

    #pragma unroll 4
    for (int it = 0; it < 16; it++) {
        const int idx = tid + it * 256;        // 0..4095
        const int b = idx >> 6;                // 0..63
        const int l = idx & 63;                // local hw
        const float4* p = x4 + (size_t)b * (HWN * 4) + (size_t)(hw0 + l) * 4;
        float4 v0 = p[0], v1 = p[1], v2 = p[2], v3 = p[3];
        float s = ((v0.x + v0.y) + (v0.z + v0.w))
                + ((v1.x + v1.y) + (v1.z + v1.w))
                + ((v2.x + v2.y) + (v2.z + v2.w))
                + ((v3.x + v3.y) + (v3.z + v3.w));
        s_s[l][b] = s;
    }
    __syncthreads();
    #pragma unroll
    for (int j = 0; j < 4; j++) {
        int idx = tid + (j << 8);          // 0..1023
        int l = idx >> 4;                  // local hw
        int b4 = (idx & 15) << 2;          // b quad
        float4 o = make_float4(s_s[l][b4], s_s[l][b4 + 1], s_s[l][b4 + 2], s_s[l][b4 + 3]);
        *reinterpret_cast<float4*>(&g_S[(size_t)(hw0 + l) * 64 + b4]) = o;
    }
}

// ============================================================================
// K2: separable Gaussian tables.  grid 128 (coord t) x 256 (u).
// ============================================================================
__global__ __launch_bounds__(256) void k2_tables(
    const float* __restrict__ a1, const float* __restrict__ a2,
    const float* __restrict__ s1, const float* __restrict__ s2,
    const float* __restrict__ ux, const float* __restrict__ uy)
{
    const int t = blockIdx.x;        // coordinate (W == H == 128)
    const int u = threadIdx.x;
    const float TWO_PI = 6.2831853071795864769f;

    float sA = s1[u];
    float sB = sA + s2[u];
    float c1 = a1[u] / (sA * TWO_PI);
    float c2 = a2[u] / (sB * TWO_PI);
    float ft = (float)t;

    float dx = ft - ux[u];
    float dx2 = 0.5f * dx * dx;
    g_GX1t[t * UU + u] = expf(-dx2 / sA);
    g_GX2t[t * UU + u] = expf(-dx2 / sB);

    float dy = ft - uy[u];
    float dy2 = 0.5f * dy * dy;
    g_GY1t[t * UU + u] =  c1 * expf(-dy2 / sA);
    g_GY2t[t * UU + u] = -c2 * expf(-dy2 / sB);
}

// ============================================================================
// K3: fused filter-build + GEMM.  One block per h row (grid 128).
// Block tile: M=64 (all b) x N=256 (all u), K=128 (w) chunked into 4x32.
// Static SMEM (40 KB). Thread tile 8b x 8u, packed fp32 inner loop.
// ============================================================================
#define KCH 32
__global__ __launch_bounds__(256) void k3_gemm() {
    __shared__ float F_s[KCH * UU];          // 32 KB
    __shared__ float S_s[KCH * BB];          //  8 KB

    const int h = blockIdx.x;
    const int tid = threadIdx.x;
    const int tu = tid & 31;                 // u octet
    const int tb = tid >> 5;                 // b octet

    const float gy1 = g_GY1t[h * UU + tid];
    const float gy2 = g_GY2t[h * UU + tid];

    ull acc[8][4];
    #pragma unroll
    for (int b = 0; b < 8; b++)
        #pragma unroll
        for (int p = 0; p < 4; p++) acc[b][p] = 0ull;

    const float* Fb = F_s + tu * 8;
    const float* Sb = S_s + tb * 8;
    const float4* Ssrc = reinterpret_cast<const float4*>(g_S + (size_t)h * (WW * BB));
    float4* Sdst = reinterpret_cast<float4*>(S_s);

    for (int kc = 0; kc < 4; kc++) {
        #pragma unroll 8
        for (int j = 0; j < KCH; j++) {
            const int w = kc * KCH + j;
            F_s[j * UU + tid] = fmaf(gy2, g_GX2t[w * UU + tid],
                                     gy1 * g_GX1t[w * UU + tid]);
        }
        Sdst[tid]       = Ssrc[kc * 512 + tid];
        Sdst[tid + 256] = Ssrc[kc * 512 + tid + 256];
        __syncthreads();

        #pragma unroll 4
        for (int k = 0; k < KCH; k++) {
            const float4 sA  = *reinterpret_cast<const float4*>(Sb + k * BB);
            const float4 sBv = *reinterpret_cast<const float4*>(Sb + k * BB + 4);
            const ulonglong2 fA = *reinterpret_cast<const ulonglong2*>(Fb + k * UU);
            const ulonglong2 fB = *reinterpret_cast<const ulonglong2*>(Fb + k * UU + 4);
            ull f[4] = { fA.x, fA.y, fB.x, fB.y };
            float sv[8] = { sA.x, sA.y, sA.z, sA.w, sBv.x, sBv.y, sBv.z, sBv.w };
            #pragma unroll
            for (int b = 0; b < 8; b++) {
                ull sd = dup2(sv[b]);
                #pragma unroll
                for (int p = 0; p < 4; p++) fma2(acc[b][p], sd, f[p]);
            }
        }
        __syncthreads();
    }

    float* Pp = g_P + (size_t)h * (BB * UU) + (tb * 8) * UU + tu * 8;
    #pragma unroll
    for (int b = 0; b < 8; b++) {
        float4 o0 = make_float4(f2lo(acc[b][0]), f2hi(acc[b][0]), f2lo(acc[b][1]), f2hi(acc[b][1]));
        float4 o1 = make_float4(f2lo(acc[b][2]), f2hi(acc[b][2]), f2lo(acc[b][3]), f2hi(acc[b][3]));
        *reinterpret_cast<float4*>(Pp + b * UU)     = o0;
        *reinterpret_cast<float4*>(Pp + b * UU + 4) = o1;
    }
}

// ============================================================================
// K4a: reduce h 128 -> 8.  32768 threads (128 blocks x 256), float4 columns.
// thread: col = global & 4095 (float4 col), seg = global >> 12 (0..7);
// sums h = seg*16 .. seg*16+15 (16 independent coalesced loads, MLP 16).
// ============================================================================
__global__ __launch_bounds__(256) void k4a_reduce() {
    const int t = blockIdx.x * 256 + threadIdx.x;   // 0..32767
    const int col = t & 4095;                       // float4 column
    const int seg = t >> 12;                        // 0..7
    const float4* P4 = reinterpret_cast<const float4*>(g_P);
    float4 a = make_float4(0.f, 0.f, 0.f, 0.f);
    #pragma unroll
    for (int j = 0; j < 16; j++) {
        float4 v = P4[(size_t)(seg * 16 + j) * 4096 + col];
        a.x += v.x; a.y += v.y; a.z += v.z; a.w += v.w;
    }
    reinterpret_cast<float4*>(g_P2)[seg * 4096 + col] = a;
}

// ============================================================================
// K4b: reduce 8 segs + bias.  4096 threads (16 blocks x 256), L2-resident.
// ============================================================================
__global__ __launch_bounds__(256) void k4b_reduce(const float* __restrict__ bias,
                                                  float* __restrict__ out) {
    const int col = blockIdx.x * 256 + threadIdx.x;   // 0..4095
    const float4* P2 = reinterpret_cast<const float4*>(g_P2);
    float4 a = P2[col];
    #pragma unroll
    for (int s = 1; s < 8; s++) {
        float4 v = P2[s * 4096 + col];
        a.x += v.x; a.y += v.y; a.z += v.z; a.w += v.w;
    }
    const int u4 = col & 63;                          // idx = b*256+u; col = b*64+u/4
    float4 bv = reinterpret_cast<const float4*>(bias)[u4];
    a.x += bv.x; a.y += bv.y; a.z += bv.z; a.w += bv.w;
    reinterpret_cast<float4*>(out)[col] = a;
}

// ============================================================================
extern "C" void kernel_launch(void* const* d_in, const int* in_sizes, int n_in,
                              void* d_out, int out_size) {
    const float* x    = (const float*)d_in[0];
    const float* a1   = (const float*)d_in[1];
    const float* a2   = (const float*)d_in[2];
    const float* s1   = (const float*)d_in[3];
    const float* s2   = (const float*)d_in[4];
    const float* ux   = (const float*)d_in[5];
    const float* uy   = (const float*)d_in[6];
    const float* bias = (const float*)d_in[7];
    float* out = (float*)d_out;

    k1_reduce_c<<<HWN / 64, 256>>>(x);
    k2_tables<<<128, 256>>>(a1, a2, s1, s2, ux, uy);
    k3_gemm<<<HH, 256>>>();
    k4a_reduce<<<128, 256>>>();
    k4b_reduce<<<16, 256>>>(bias, out);
}